// round 16
// baseline (speedup 1.0000x reference)
#include <cuda_runtime.h>
#include <cuda.h>
#include <dlfcn.h>
#include <cstdint>
#include <math.h>

#define B_BATCH 4096
#define HID     512
#define G4      2048
#define BM      128
#define BN      256
#define KC      32
#define NCHUNK  16
#define NTILES  768       // 3 steps (5,6,7) x 256 tiles
#define NWORK   148

#define STG_BYTES  98304
#define STG(s)     ((s) * STG_BYTES)
#define OFF_AHI    0
#define OFF_ALO    16384
#define OFF_BHI    32768
#define OFF_BLO    65536
#define OFF_MBAR   196608
#define OFF_ES     196672
#define ES_PITCH   260
#define OFF_DWS    (OFF_ES + 9 * ES_PITCH * 4)
#define SMEM_TOTAL (OFF_DWS + 13 * 64 * 4)
#define D_PITCH    264
#define CHUNK_BYTES 98304u

// ---------------- device scratch ----------------
__device__ __align__(1024) float g_E[9 * G4];
__device__ __align__(1024) float g_c[B_BATCH * HID];
__device__ __align__(1024) float g_Ah[2][B_BATCH * HID];
__device__ __align__(1024) float g_Al[2][B_BATCH * HID];
__device__ __align__(1024) float g_Bh[G4 * HID];
__device__ __align__(1024) float g_Bl[G4 * HID];
__device__ __align__(1024) float g_part[8 * B_BATCH * 16];
__device__ __align__(1024) float g_Hd[2][512 * HID];
__device__ __align__(1024) float g_Cd[2][512 * HID];
__device__ __align__(1024) float g_G[512 * G4];
__device__ float g_dlog[512 * 20];
__device__ float g_dec0[16];
__device__ int g_tok[B_BATCH];
__device__ int g_key[B_BATCH];
__device__ int g_done[32];
__device__ int g_ready[4][32];
__device__ int g_ticket;

// ---------------- helpers ----------------
__device__ __forceinline__ uint32_t smem_u32(const void* p){
    uint32_t a; asm("{ .reg .u64 t; cvta.to.shared.u64 t, %1; cvt.u32.u64 %0, t; }" : "=r"(a) : "l"(p));
    return a;
}
__device__ __forceinline__ float tf32_rna(float x){
    uint32_t t; asm("cvt.rna.tf32.f32 %0, %1;" : "=r"(t) : "f"(x));
    return __uint_as_float(t);
}
__device__ __forceinline__ float sigf(float x){ return __fdividef(1.0f, 1.0f + __expf(-x)); }
__device__ __forceinline__ float tanhfa(float x){ return 2.0f * __fdividef(1.0f, 1.0f + __expf(-2.0f * x)) - 1.0f; }

#define LDSM4(r0, r1, r2, r3, addr) \
    asm volatile("ldmatrix.sync.aligned.m8n8.x4.shared.b16 {%0,%1,%2,%3}, [%4];" \
        : "=r"(r0), "=r"(r1), "=r"(r2), "=r"(r3) : "r"(addr))

#define MMA_TF32(d, a, b) \
    asm volatile("mma.sync.aligned.m16n8k8.row.col.f32.tf32.tf32.f32 " \
        "{%0,%1,%2,%3}, {%4,%5,%6,%7}, {%8,%9}, {%0,%1,%2,%3};" \
        : "+f"((d)[0]), "+f"((d)[1]), "+f"((d)[2]), "+f"((d)[3]) \
        : "r"((a)[0]), "r"((a)[1]), "r"((a)[2]), "r"((a)[3]), "r"((b)[0]), "r"((b)[1]))

#define MBAR_INIT(mb, n) asm volatile("mbarrier.init.shared.b64 [%0], %1;" :: "r"((uint32_t)(mb)), "r"((uint32_t)(n)) : "memory")
#define MBAR_EXPECT_TX(mb, bytes) asm volatile("mbarrier.arrive.expect_tx.shared.b64 _, [%0], %1;" :: "r"((uint32_t)(mb)), "r"((uint32_t)(bytes)) : "memory")
#define MBAR_ARRIVE(mb) asm volatile("mbarrier.arrive.shared.b64 _, [%0];" :: "r"((uint32_t)(mb)) : "memory")
#define MBAR_WAIT(mb, par) do { \
    uint32_t _m = (uint32_t)(mb); uint32_t _p = (uint32_t)(par); uint32_t _d; \
    asm volatile("{\n\t.reg .pred p;\n\tmbarrier.try_wait.parity.acquire.cta.shared::cta.b64 p, [%1], %2;\n\tselp.b32 %0, 1, 0, p;\n\t}" \
        : "=r"(_d) : "r"(_m), "r"(_p) : "memory"); \
    if (!_d) { \
        asm volatile("{\n\t.reg .pred P1;\n\tWL_%=:\n\tmbarrier.try_wait.parity.acquire.cta.shared::cta.b64 P1, [%0], %1, 0x989680;\n\t@P1 bra.uni WD_%=;\n\tbra.uni WL_%=;\n\tWD_%=:\n\t}" \
            :: "r"(_m), "r"(_p) : "memory"); \
    } } while (0)

#define TMA_2D(dst, map, cx, cy, mb) \
    asm volatile("cp.async.bulk.tensor.2d.shared::cta.global.tile.mbarrier::complete_tx::bytes " \
        "[%0], [%1, {%2, %3}], [%4];" \
        :: "r"((uint32_t)(dst)), "l"(map), "r"((int32_t)(cx)), "r"((int32_t)(cy)), "r"((uint32_t)(mb)) : "memory")

// ---------------- E = emb @ w_ih^T + b_ih + b_hh ----------------
__global__ void precompute_E(const float* __restrict__ emb, const float* __restrict__ w_ih,
                             const float* __restrict__ b_ih, const float* __restrict__ b_hh){
    __shared__ float er[HID];
    int t = blockIdx.y;
    int j = blockIdx.x * blockDim.x + threadIdx.x;
    for (int k = threadIdx.x; k < HID; k += blockDim.x) er[k] = emb[t * HID + k];
    __syncthreads();
    const float* w = w_ih + (size_t)j * HID;
    float s = 0.f;
    #pragma unroll 4
    for (int k = 0; k < HID; k += 4){
        float4 wv = *(const float4*)(w + k);
        s += er[k]*wv.x + er[k+1]*wv.y + er[k+2]*wv.z + er[k+3]*wv.w;
    }
    g_E[t * G4 + j] = s + b_ih[j] + b_hh[j];
}

// ---------------- split + permute w_hh ----------------
__global__ void split_B(const float* __restrict__ w_hh){
    int r = blockIdx.x;
    int t = r >> 8, n = r & 255;
    int srow = (n >> 6) * HID + t * 64 + (n & 63);
    const float* s = w_hh + (size_t)srow * HID;
    float* dh = g_Bh + (size_t)r * HID;
    float* dl = g_Bl + (size_t)r * HID;
    for (int k = threadIdx.x; k < HID; k += blockDim.x){
        float w = s[k];
        float hi = tf32_rna(w);
        dh[k] = hi;
        dl[k] = tf32_rna(w - hi);
    }
}

// ---------------- step 0 ----------------
__global__ void step0_compute(const float* __restrict__ wn2, const float* __restrict__ bn2,
                              const float* __restrict__ wop0, const float* __restrict__ bop0){
    __shared__ float sh[HID];
    __shared__ float lg[10];
    int k = threadIdx.x;
    float i_ = sigf(g_E[k]);
    float gg = tanhfa(g_E[1024 + k]);
    float o_ = sigf(g_E[1536 + k]);
    float cc = i_ * gg;
    float hh = o_ * tanhfa(cc);
    sh[k] = hh;
    g_Hd[0][k] = hh;
    g_Cd[0][k] = cc;
    __syncthreads();
    int wid = k >> 5, lane = k & 31;
    if (wid < 10){
        const float* wr = (wid < 2) ? wn2 + wid * HID : wop0 + (wid - 2) * HID;
        float s = 0.f;
        #pragma unroll
        for (int j = 0; j < 16; ++j){
            int col = lane + (j << 5);
            s += sh[col] * wr[col];
        }
        #pragma unroll
        for (int off = 16; off > 0; off >>= 1) s += __shfl_xor_sync(0xffffffffu, s, off);
        if (lane == 0) lg[wid] = s;
    }
    __syncthreads();
    if (k == 0){
        float l0[2], l1[8];
        for (int w = 0; w < 2; ++w) l0[w] = 2.5f * tanhf((lg[w] + bn2[w]) * 0.2f);
        for (int w = 0; w < 8; ++w) l1[w] = (lg[2 + w] + bop0[w]) * 0.2f;
        float m0 = fmaxf(l0[0], l0[1]);
        float s0 = expf(l0[0] - m0) + expf(l0[1] - m0);
        float lse0 = m0 + logf(s0);
        float e0 = 0.f;
        for (int w = 0; w < 2; ++w){ float lp = l0[w] - lse0; e0 -= lp * expf(lp); }
        float m1 = l1[0]; for (int w = 1; w < 8; ++w) m1 = fmaxf(m1, l1[w]);
        float s1 = 0.f; for (int w = 0; w < 8; ++w) s1 += expf(l1[w] - m1);
        float lse1 = m1 + logf(s1);
        float e1 = 0.f;
        for (int w = 0; w < 8; ++w){ float lp = l1[w] - lse1; e1 -= lp * expf(lp); }
        g_dec0[0] = l0[0]; g_dec0[1] = l0[1];
        for (int w = 0; w < 8; ++w) g_dec0[2 + w] = l1[w];
        g_dec0[10] = lse0; g_dec0[11] = lse1;
        g_dec0[12] = e0;   g_dec0[13] = e1;
    }
}

__global__ void step0_sample(const float* __restrict__ gum, float* __restrict__ out){
    int b = blockIdx.x * 256 + threadIdx.x;
    float l0[2], l1[8];
    l0[0] = g_dec0[0]; l0[1] = g_dec0[1];
    #pragma unroll
    for (int w = 0; w < 8; ++w) l1[w] = g_dec0[2 + w];
    float lse0 = g_dec0[10], lse1 = g_dec0[11];
    float e0 = g_dec0[12], e1 = g_dec0[13];
    const float* g0 = gum + (size_t)b * 8;
    const float* g1 = gum + ((size_t)B_BATCH + b) * 8;
    int a0 = (l0[1] + g0[1] > l0[0] + g0[0]) ? 1 : 0;
    out[b]                         = (float)a0;
    out[(size_t)16 * B_BATCH + b]  = l0[a0] - lse0;
    out[(size_t)32 * B_BATCH + b]  = e0;
    int a1 = 0; float best = l1[0] + g1[0];
    #pragma unroll
    for (int w = 1; w < 8; ++w){ float v = l1[w] + g1[w]; if (v > best){ best = v; a1 = w; } }
    out[(size_t)1 * B_BATCH + b]   = (float)a1;
    out[(size_t)17 * B_BATCH + b]  = l1[a1] - lse1;
    out[(size_t)33 * B_BATCH + b]  = e1;
    g_key[b] = a1;
}

// ---------------- distinct-state steps 1..4 ----------------
__global__ __launch_bounds__(256)
void dstep_gemm(const float* __restrict__ w_hh, const float* __restrict__ Hd, int Kin){
    __shared__ float hs[8][HID];
    __shared__ float ws[256][17];
    int tid = threadIdx.x;
    int j0 = blockIdx.x * 256;
    int kb = blockIdx.y * 8;
    int nk = Kin - kb; if (nk > 8) nk = 8;
    for (int idx = tid; idx < nk * HID; idx += 256)
        hs[idx >> 9][idx & 511] = Hd[(size_t)(kb + (idx >> 9)) * HID + (idx & 511)];
    float acc[8] = {0,0,0,0,0,0,0,0};
    for (int kc = 0; kc < HID; kc += 16){
        __syncthreads();
        #pragma unroll
        for (int i = 0; i < 16; ++i){
            int e = tid + 256 * i;
            ws[e >> 4][e & 15] = w_hh[(size_t)(j0 + (e >> 4)) * HID + kc + (e & 15)];
        }
        __syncthreads();
        #pragma unroll
        for (int kl = 0; kl < 16; ++kl){
            float w = ws[tid][kl];
            #pragma unroll
            for (int q = 0; q < 8; ++q) acc[q] += w * hs[q][kc + kl];
        }
    }
    for (int q = 0; q < nk; ++q) g_G[(size_t)(kb + q) * G4 + j0 + tid] = acc[q];
}

__global__ __launch_bounds__(128)
void dstep_point(int Kin, int kd,
                 const float* __restrict__ wn, const float* __restrict__ bn,
                 const float* __restrict__ wop, const float* __restrict__ bop,
                 float* __restrict__ Hdo, float* __restrict__ Cdo,
                 const float* __restrict__ Cdi){
    __shared__ float sh[HID];
    __shared__ float hd[13];
    int kp = blockIdx.x;
    int k = kp % Kin, t = kp / Kin;
    int tid = threadIdx.x;
    const float* Gr = &g_G[(size_t)k * G4];
    const float* Er = &g_E[(size_t)t * G4];
    const float* Cr = &Cdi[(size_t)k * HID];
    #pragma unroll
    for (int e = 0; e < 4; ++e){
        int col = tid * 4 + e;
        float gi = Gr[col]        + Er[col];
        float gf = Gr[512 + col]  + Er[512 + col];
        float gg = Gr[1024 + col] + Er[1024 + col];
        float go = Gr[1536 + col] + Er[1536 + col];
        float i_ = sigf(gi), f_ = sigf(gf);
        float g_ = tanhfa(gg), o_ = sigf(go);
        float cc = f_ * Cr[col] + i_ * g_;
        float hh = o_ * tanhfa(cc);
        sh[col] = hh;
        Hdo[(size_t)kp * HID + col] = hh;
        Cdo[(size_t)kp * HID + col] = cc;
    }
    __syncthreads();
    int wid = tid >> 5, lane = tid & 31;
    for (int hx = wid; hx < 13; hx += 4){
        if (hx < 5 && hx >= kd) continue;
        const float* wr = (hx < 5) ? wn + hx * HID : wop + (hx - 5) * HID;
        float s = 0.f;
        #pragma unroll
        for (int j = 0; j < 16; ++j){
            int col = lane + (j << 5);
            s += sh[col] * wr[col];
        }
        #pragma unroll
        for (int off = 16; off > 0; off >>= 1) s += __shfl_xor_sync(0xffffffffu, s, off);
        if (lane == 0) hd[hx] = s;
    }
    __syncthreads();
    if (tid == 0){
        float* dl = &g_dlog[kp * 20];
        float ln[5], lo[8];
        for (int w = 0; w < kd; ++w) ln[w] = 2.5f * tanhf((hd[w] + bn[w]) * 0.2f);
        for (int w = 0; w < 8; ++w)  lo[w] = (hd[5 + w] + bop[w]) * 0.2f;
        float m = ln[0]; for (int w = 1; w < kd; ++w) m = fmaxf(m, ln[w]);
        float sum = 0.f; for (int w = 0; w < kd; ++w) sum += expf(ln[w] - m);
        float lse_n = m + logf(sum);
        float ent_n = 0.f;
        for (int w = 0; w < kd; ++w){ float lp = ln[w] - lse_n; ent_n -= lp * expf(lp); }
        m = lo[0]; for (int w = 1; w < 8; ++w) m = fmaxf(m, lo[w]);
        sum = 0.f; for (int w = 0; w < 8; ++w) sum += expf(lo[w] - m);
        float lse_o = m + logf(sum);
        float ent_o = 0.f;
        for (int w = 0; w < 8; ++w){ float lp = lo[w] - lse_o; ent_o -= lp * expf(lp); }
        for (int w = 0; w < kd; ++w) dl[w] = ln[w];
        for (int w = 0; w < 8; ++w)  dl[5 + w] = lo[w];
        dl[13] = lse_n; dl[14] = lse_o; dl[15] = ent_n; dl[16] = ent_o;
    }
}

__global__ void dsample(int s, int K, int kd, const float* __restrict__ gum, float* __restrict__ out){
    int b = blockIdx.x * 256 + threadIdx.x;
    int k = g_key[b];
    const float* dl = &g_dlog[k * 20];
    const float* g0 = gum + ((size_t)(2 * s) * B_BATCH + b) * 8;
    int a = 0; float best = dl[0] + g0[0];
    for (int w = 1; w < kd; ++w){ float v = dl[w] + g0[w]; if (v > best){ best = v; a = w; } }
    int row = 2 * s;
    out[(size_t)row * B_BATCH + b]        = (float)a;
    out[(size_t)(16 + row) * B_BATCH + b] = dl[a] - dl[13];
    out[(size_t)(32 + row) * B_BATCH + b] = dl[15];
    const float* g1 = gum + ((size_t)(2 * s + 1) * B_BATCH + b) * 8;
    a = 0; best = dl[5] + g1[0];
    #pragma unroll
    for (int w = 1; w < 8; ++w){ float v = dl[5 + w] + g1[w]; if (v > best){ best = v; a = w; } }
    row = 2 * s + 1;
    out[(size_t)row * B_BATCH + b]        = (float)a;
    out[(size_t)(16 + row) * B_BATCH + b] = dl[5 + a] - dl[14];
    out[(size_t)(32 + row) * B_BATCH + b] = dl[16];
    g_key[b] = k + K * a;
    g_tok[b] = a;
}

// ---------------- step 4: per-row pointwise from distinct G + inline decide ----------------
// key = key3 + 512*t4. Writes per-row c5/Ah/Al (ping 1), decides step 4, sets g_tok.
__global__ __launch_bounds__(128)
void row_point4(const float* __restrict__ wn, const float* __restrict__ bn,
                const float* __restrict__ wop, const float* __restrict__ bop,
                const float* __restrict__ gum, float* __restrict__ out){
    __shared__ float sh[HID];
    __shared__ float hd[12];
    int b = blockIdx.x;
    int tid = threadIdx.x;
    if (b == 0){
        if (tid < 128) ((int*)g_ready)[tid] = 0;
        if (tid == 0) g_ticket = 0;
    }
    int key = g_key[b];
    int k3 = key & 511, t4 = key >> 9;
    const float* Gr = &g_G[(size_t)k3 * G4];
    const float* Er = &g_E[(size_t)t4 * G4];
    const float* Cr = &g_Cd[1][(size_t)k3 * HID];
    size_t gb = (size_t)b << 9;
    int col0 = tid * 4;
    float4 cn, ah, al;
    #pragma unroll
    for (int e = 0; e < 4; ++e){
        int col = col0 + e;
        float gi = Gr[col]        + Er[col];
        float gf = Gr[512 + col]  + Er[512 + col];
        float gg = Gr[1024 + col] + Er[1024 + col];
        float go = Gr[1536 + col] + Er[1536 + col];
        float i_ = sigf(gi), f_ = sigf(gf);
        float g_ = tanhfa(gg), o_ = sigf(go);
        float cc = f_ * Cr[col] + i_ * g_;
        float hh = o_ * tanhfa(cc);
        sh[col] = hh;
        (&cn.x)[e] = cc;
        float hi = tf32_rna(hh);
        (&ah.x)[e] = hi; (&al.x)[e] = tf32_rna(hh - hi);
    }
    *(float4*)&g_c[gb + col0]     = cn;
    *(float4*)&g_Ah[1][gb + col0] = ah;
    *(float4*)&g_Al[1][gb + col0] = al;
    __syncthreads();
    int wid = tid >> 5, lane = tid & 31;
    for (int hx = wid; hx < 12; hx += 4){
        const float* wr = (hx < 4) ? wn + hx * HID : wop + (hx - 4) * HID;
        float s = 0.f;
        #pragma unroll
        for (int j = 0; j < 16; ++j){
            int col = lane + (j << 5);
            s += sh[col] * wr[col];
        }
        #pragma unroll
        for (int off = 16; off > 0; off >>= 1) s += __shfl_xor_sync(0xffffffffu, s, off);
        if (lane == 0) hd[hx] = s;
    }
    __syncthreads();
    if (tid == 0){
        float l[8];
        for (int w = 0; w < 4; ++w) l[w] = 2.5f * tanhf((hd[w] + bn[w]) * 0.2f);
        {
            const float* g0 = gum + ((size_t)8 * B_BATCH + b) * 8;
            float m = l[0]; for (int w = 1; w < 4; ++w) m = fmaxf(m, l[w]);
            float sum = 0.f; for (int w = 0; w < 4; ++w) sum += expf(l[w] - m);
            float lse = m + logf(sum);
            float ent = 0.f;
            for (int w = 0; w < 4; ++w){ float lp = l[w] - lse; ent -= lp * expf(lp); }
            int a = 0; float best = l[0] + g0[0];
            for (int w = 1; w < 4; ++w){ float v = l[w] + g0[w]; if (v > best){ best = v; a = w; } }
            out[(size_t)8 * B_BATCH + b]  = (float)a;
            out[(size_t)24 * B_BATCH + b] = l[a] - lse;
            out[(size_t)40 * B_BATCH + b] = ent;
        }
        for (int w = 0; w < 8; ++w) l[w] = (hd[4 + w] + bop[w]) * 0.2f;
        {
            const float* g1 = gum + ((size_t)9 * B_BATCH + b) * 8;
            float m = l[0]; for (int w = 1; w < 8; ++w) m = fmaxf(m, l[w]);
            float sum = 0.f; for (int w = 0; w < 8; ++w) sum += expf(l[w] - m);
            float lse = m + logf(sum);
            float ent = 0.f;
            for (int w = 0; w < 8; ++w){ float lp = l[w] - lse; ent -= lp * expf(lp); }
            int a = 0; float best = l[0] + g1[0];
            for (int w = 1; w < 8; ++w){ float v = l[w] + g1[w]; if (v > best){ best = v; a = w; } }
            out[(size_t)9 * B_BATCH + b]  = (float)a;
            out[(size_t)25 * B_BATCH + b] = l[a] - lse;
            out[(size_t)41 * B_BATCH + b] = ent;
            g_tok[b] = a;
        }
    }
}

// ---------------- persistent mega-kernel: steps 5..7 ----------------
__global__ __launch_bounds__(256, 1)
void mega_step(const float* __restrict__ wn2p, const float* __restrict__ wn3p,
               const float* __restrict__ bn2p, const float* __restrict__ bn3p,
               const float* __restrict__ wop, const float* __restrict__ bop,
               const float* __restrict__ gum, float* __restrict__ out,
               const __grid_constant__ CUtensorMap mAh0,
               const __grid_constant__ CUtensorMap mAh1,
               const __grid_constant__ CUtensorMap mAl0,
               const __grid_constant__ CUtensorMap mAl1,
               const __grid_constant__ CUtensorMap mBh,
               const __grid_constant__ CUtensorMap mBl){
    extern __shared__ __align__(1024) char smem[];
    uint32_t sb = smem_u32(smem);
    int tid = threadIdx.x, wid = tid >> 5, lane = tid & 31;

    float* Es  = (float*)(smem + OFF_ES);
    float* dws = (float*)(smem + OFF_DWS);
    __shared__ int s_tile;

    uint32_t fullb  = sb + OFF_MBAR;
    uint32_t emptyb = sb + OFF_MBAR + 16;
    if (tid == 0){
        MBAR_INIT(fullb, 1);
        MBAR_INIT(fullb + 8, 1);
        MBAR_INIT(emptyb, 8);
        MBAR_INIT(emptyb + 8, 8);
    }
    __syncthreads();

    int pfA = 0, pfB = 0;
    int peA = 0, peB = 0;
    int first = 1;

    int wm = wid >> 2, wn = wid & 3;
    int mat = lane >> 3, r8 = lane & 7;
    int rowA[4];
    #pragma unroll
    for (int f = 0; f < 4; ++f) rowA[f] = wm * 64 + f * 16 + ((mat & 1) << 3) + r8;
    int usA = mat >> 1;
    int rowB[4];
    #pragma unroll
    for (int p = 0; p < 4; ++p) rowB[p] = wn * 64 + (p * 2 + (mat >> 1)) * 8 + r8;
    int usB = mat & 1;

    for (;;){
        if (tid == 0) s_tile = atomicAdd(&g_ticket, 1);
        __syncthreads();
        int t = s_tile;
        if (t >= NTILES) break;
        int s  = 5 + (t >> 8);
        int r  = t & 255;
        int bx = r & 7;
        int y  = r >> 3;
        int R0 = y * BM;
        int N0 = bx * BN;
        int c0 = bx * 64;
        int sIn = s & 1;
        int i  = s >> 1;           // 2 (s=5) or 3 (s=6,7)
        int kd = i + 2;
        const float* wnp  = (i == 2) ? wn2p : wn3p;
        const float* wopp = wop + (size_t)i * 8 * HID;
        const CUtensorMap* pAh = sIn ? &mAh1 : &mAh0;
        const CUtensorMap* pAl = sIn ? &mAl1 : &mAl0;

        // dep wait: all 8 column tiles of (s-1, y) complete
        if (s > 5 && tid == 0){
            while (atomicAdd(&g_ready[s - 6][y], 0) != 8) {}
            __threadfence();
        }
        __syncthreads();

        // TMA prologue: chunks 0,1
        if (tid == 0){
            if (!first){ MBAR_WAIT(emptyb, peA); peA ^= 1; }
            MBAR_EXPECT_TX(fullb, CHUNK_BYTES);
            TMA_2D(sb + STG(0) + OFF_AHI, pAh, 0, R0, fullb);
            TMA_2D(sb + STG(0) + OFF_ALO, pAl, 0, R0, fullb);
            TMA_2D(sb + STG(0) + OFF_BHI, &mBh, 0, N0, fullb);
            TMA_2D(sb + STG(0) + OFF_BLO, &mBl, 0, N0, fullb);
            if (!first){ MBAR_WAIT(emptyb + 8, peB); peB ^= 1; }
            MBAR_EXPECT_TX(fullb + 8, CHUNK_BYTES);
            TMA_2D(sb + STG(1) + OFF_AHI, pAh, KC, R0, fullb + 8);
            TMA_2D(sb + STG(1) + OFF_ALO, pAl, KC, R0, fullb + 8);
            TMA_2D(sb + STG(1) + OFF_BHI, &mBh, KC, N0, fullb + 8);
            TMA_2D(sb + STG(1) + OFF_BLO, &mBl, KC, N0, fullb + 8);
        }

        // in-kernel finalize for step s-1 (bx==0 tiles, warps 4-7)
        if (s > 5 && bx == 0 && tid >= 128){
            int iP = (s - 1) >> 1;
            int kdPrev = iP + 2;
            const float* bnPrev  = (iP == 2) ? bn2p : bn3p;
            const float* bopPrev = bop + iP * 8;
            int b = R0 + tid - 128;
            float dn[5] = {0,0,0,0,0};
            float dq[8] = {0,0,0,0,0,0,0,0};
            #pragma unroll
            for (int bx2 = 0; bx2 < 8; ++bx2){
                const float4* p = (const float4*)&g_part[((size_t)bx2 * B_BATCH + b) * 16];
                float4 p0 = p[0], p1 = p[1], p2 = p[2], p3 = p[3];
                dn[0] += p0.x; dn[1] += p0.y; dn[2] += p0.z; dn[3] += p0.w;
                dn[4] += p1.x;
                dq[0] += p1.y; dq[1] += p1.z; dq[2] += p1.w;
                dq[3] += p2.x; dq[4] += p2.y; dq[5] += p2.z; dq[6] += p2.w;
                dq[7] += p3.x;
            }
            float l[8];
            for (int w = 0; w < kdPrev; ++w) l[w] = 2.5f * tanhf((dn[w] + bnPrev[w]) * 0.2f);
            {
                const float* g0 = gum + ((size_t)(2 * (s - 1)) * B_BATCH + b) * 8;
                float m = l[0]; for (int w = 1; w < kdPrev; ++w) m = fmaxf(m, l[w]);
                float sum = 0.f; for (int w = 0; w < kdPrev; ++w) sum += expf(l[w] - m);
                float lse = m + logf(sum);
                float ent = 0.f;
                for (int w = 0; w < kdPrev; ++w){ float lp = l[w] - lse; ent -= lp * expf(lp); }
                int a = 0; float best = l[0] + g0[0];
                for (int w = 1; w < kdPrev; ++w){ float v = l[w] + g0[w]; if (v > best){ best = v; a = w; } }
                int rw = 2 * (s - 1);
                out[(size_t)rw * B_BATCH + b]        = (float)a;
                out[(size_t)(16 + rw) * B_BATCH + b] = l[a] - lse;
                out[(size_t)(32 + rw) * B_BATCH + b] = ent;
            }
            for (int w = 0; w < 8; ++w) l[w] = (dq[w] + bopPrev[w]) * 0.2f;
            {
                const float* g1 = gum + ((size_t)(2 * (s - 1) + 1) * B_BATCH + b) * 8;
                float m = l[0]; for (int w = 1; w < 8; ++w) m = fmaxf(m, l[w]);
                float sum = 0.f; for (int w = 0; w < 8; ++w) sum += expf(l[w] - m);
                float lse = m + logf(sum);
                float ent = 0.f;
                for (int w = 0; w < 8; ++w){ float lp = l[w] - lse; ent -= lp * expf(lp); }
                int a = 0; float best = l[0] + g1[0];
                for (int w = 1; w < 8; ++w){ float v = l[w] + g1[w]; if (v > best){ best = v; a = w; } }
                int rw = 2 * (s - 1) + 1;
                out[(size_t)rw * B_BATCH + b]        = (float)a;
                out[(size_t)(16 + rw) * B_BATCH + b] = l[a] - lse;
                out[(size_t)(32 + rw) * B_BATCH + b] = ent;
                g_tok[b] = a;
            }
            asm volatile("bar.sync 1, 128;" ::: "memory");
            if (tid == 128){
                __threadfence();
                atomicExch(&g_done[y], s);
            }
        }

        // prologue gathers
        for (int idx = tid; idx < 9 * 256; idx += 256){
            int tt = idx >> 8, n = idx & 255;
            Es[tt * ES_PITCH + n] = g_E[tt * G4 + (n >> 6) * HID + c0 + (n & 63)];
        }
        for (int idx = tid; idx < 13 * 64; idx += 256){
            int w = idx >> 6, j = idx & 63;
            float v;
            if (w < 5) v = (w < kd) ? wnp[w * HID + c0 + j] : 0.0f;
            else       v = wopp[(w - 5) * HID + c0 + j];
            dws[idx] = v;
        }

        float acc[4][8][4];
        #pragma unroll
        for (int f = 0; f < 4; ++f)
            #pragma unroll
            for (int j = 0; j < 8; ++j)
                #pragma unroll
                for (int e = 0; e < 4; ++e) acc[f][j][e] = 0.0f;

        #pragma unroll 1
        for (int c = 0; c < NCHUNK; ++c){
            int stg = c & 1;
            if (stg == 0){ MBAR_WAIT(fullb, pfA); pfA ^= 1; }
            else         { MBAR_WAIT(fullb + 8, pfB); pfB ^= 1; }

            uint32_t ahi_b = sb + STG(stg) + OFF_AHI;
            uint32_t alo_b = sb + STG(stg) + OFF_ALO;
            uint32_t bhi_b = sb + STG(stg) + OFF_BHI;
            uint32_t blo_b = sb + STG(stg) + OFF_BLO;

            #pragma unroll
            for (int ss = 0; ss < 4; ++ss){
                int ku = ss * 2;
                uint32_t ah[4][4], bh[8][2];
                #pragma unroll
                for (int f = 0; f < 4; ++f){
                    uint32_t ad = ahi_b + rowA[f] * 128 + (((ku + usA) ^ r8) << 4);
                    LDSM4(ah[f][0], ah[f][1], ah[f][2], ah[f][3], ad);
                }
                #pragma unroll
                for (int p = 0; p < 4; ++p){
                    uint32_t bd = bhi_b + rowB[p] * 128 + (((ku + usB) ^ r8) << 4);
                    LDSM4(bh[2*p][0], bh[2*p][1], bh[2*p+1][0], bh[2*p+1][1], bd);
                }
                #pragma unroll
                for (int f = 0; f < 4; ++f)
                    #pragma unroll
                    for (int j = 0; j < 8; ++j)
                        MMA_TF32(acc[f][j], ah[f], bh[j]);
                {
                    uint32_t al[4][4];
                    #pragma unroll
                    for (int f = 0; f < 4; ++f){
                        uint32_t ad = alo_b + rowA[f] * 128 + (((ku + usA) ^ r8) << 4);
                        LDSM4(al[f][0], al[f][1], al[f][2], al[f][3], ad);
                    }
                    #pragma unroll
                    for (int f = 0; f < 4; ++f)
                        #pragma unroll
                        for (int j = 0; j < 8; ++j)
                            MMA_TF32(acc[f][j], al[f], bh[j]);
                }
                {
                    uint32_t bl[8][2];
                    #pragma unroll
                    for (int p = 0; p < 4; ++p){
                        uint32_t bd = blo_b + rowB[p] * 128 + (((ku + usB) ^ r8) << 4);
                        LDSM4(bl[2*p][0], bl[2*p][1], bl[2*p+1][0], bl[2*p+1][1], bd);
                    }
                    #pragma unroll
                    for (int f = 0; f < 4; ++f)
                        #pragma unroll
                        for (int j = 0; j < 8; ++j)
                            MMA_TF32(acc[f][j], ah[f], bl[j]);
                }
            }

            if (lane == 0 && c < NCHUNK - 2) MBAR_ARRIVE(emptyb + stg * 8);
            if (tid == 0 && c + 2 < NCHUNK){
                if (stg == 0){ MBAR_WAIT(emptyb, peA); peA ^= 1; }
                else         { MBAR_WAIT(emptyb + 8, peB); peB ^= 1; }
                int cn = c + 2;
                uint32_t mb = fullb + stg * 8;
                uint32_t st = sb + STG(stg);
                MBAR_EXPECT_TX(mb, CHUNK_BYTES);
                TMA_2D(st + OFF_AHI, pAh, cn * KC, R0, mb);
                TMA_2D(st + OFF_ALO, pAl, cn * KC, R0, mb);
                TMA_2D(st + OFF_BHI, &mBh, cn * KC, N0, mb);
                TMA_2D(st + OFF_BLO, &mBl, cn * KC, N0, mb);
            }
        }

        // token wait (siblings of bx==0's finalize)
        if (s > 5 && bx != 0 && tid == 0){
            while (atomicAdd(&g_done[y], 0) != s) {}
            __threadfence();
        }
        __syncthreads();
        float* Ds = (float*)smem;
        #pragma unroll
        for (int f = 0; f < 4; ++f){
            int r0 = wm * 64 + f * 16 + (lane >> 2);
            #pragma unroll
            for (int j = 0; j < 8; ++j){
                int cb = wn * 64 + j * 8 + 2 * (lane & 3);
                *(float2*)&Ds[r0 * D_PITCH + cb]       = make_float2(acc[f][j][0], acc[f][j][1]);
                *(float2*)&Ds[(r0 + 8) * D_PITCH + cb] = make_float2(acc[f][j][2], acc[f][j][3]);
            }
        }
        __syncthreads();

        int row  = tid >> 1;
        int j0   = (tid & 1) * 32;
        int tk   = g_tok[R0 + row];
        const float* Ep = &Es[tk * ES_PITCH];
        const float* Dr = &Ds[row * D_PITCH];
        size_t gb = ((size_t)(R0 + row) << 9) + c0;
        float* Aho = &g_Ah[sIn ^ 1][0];
        float* Alo_o = &g_Al[sIn ^ 1][0];
        float hbuf[32];
        #pragma unroll
        for (int jj = 0; jj < 32; jj += 4){
            int j = j0 + jj;
            float4 iv = *(const float4*)&Dr[j];
            float4 fv = *(const float4*)&Dr[64 + j];
            float4 gv = *(const float4*)&Dr[128 + j];
            float4 ov = *(const float4*)&Dr[192 + j];
            float4 cv = *(const float4*)&g_c[gb + j];
            float4 cn, ah, al;
            #pragma unroll
            for (int e = 0; e < 4; ++e){
                float i_ = sigf((&iv.x)[e] + Ep[j + e]);
                float f_ = sigf((&fv.x)[e] + Ep[64 + j + e]);
                float gg = tanhfa((&gv.x)[e] + Ep[128 + j + e]);
                float o_ = sigf((&ov.x)[e] + Ep[192 + j + e]);
                float cc = f_ * ((&cv.x)[e]) + i_ * gg;
                float hh = o_ * tanhfa(cc);
                float hi = tf32_rna(hh);
                hbuf[jj + e] = hh;
                (&cn.x)[e] = cc;
                (&ah.x)[e] = hi; (&al.x)[e] = tf32_rna(hh - hi);
            }
            *(float4*)&g_c[gb + j]   = cn;
            *(float4*)&Aho[gb + j]   = ah;
            *(float4*)&Alo_o[gb + j] = al;
        }

        float pd[13];
        #pragma unroll
        for (int w = 0; w < 13; ++w) pd[w] = 0.0f;
        #pragma unroll
        for (int jj = 0; jj < 32; ++jj){
            float hv = hbuf[jj];
            const float* dc = &dws[j0 + jj];
            #pragma unroll
            for (int w = 0; w < 13; ++w) pd[w] += hv * dc[w * 64];
        }
        #pragma unroll
        for (int w = 0; w < 13; ++w) pd[w] += __shfl_xor_sync(0xffffffffu, pd[w], 1);
        if ((tid & 1) == 0){
            float4* dst = (float4*)&g_part[((size_t)bx * B_BATCH + R0 + row) * 16];
            dst[0] = make_float4(pd[0], pd[1], pd[2], pd[3]);
            dst[1] = make_float4(pd[4], pd[5], pd[6], pd[7]);
            dst[2] = make_float4(pd[8], pd[9], pd[10], pd[11]);
            dst[3] = make_float4(pd[12], 0.f, 0.f, 0.f);
        }

        __syncthreads();
        if (lane == 0){ MBAR_ARRIVE(emptyb); MBAR_ARRIVE(emptyb + 8); }
        if (tid == 0){
            __threadfence();
            atomicAdd(&g_ready[s - 5][y], 1);
        }
        first = 0;
    }
}

// ---------------- finalize (last step only) ----------------
__global__ __launch_bounds__(256)
void finalize_kernel(const float* __restrict__ bn, int k,
                     const float* __restrict__ bop,
                     const float* __restrict__ gum, int s, float* __restrict__ out){
    int b = blockIdx.x * 256 + threadIdx.x;
    float dn[5] = {0,0,0,0,0};
    float dq[8] = {0,0,0,0,0,0,0,0};
    #pragma unroll
    for (int bx = 0; bx < 8; ++bx){
        const float4* p = (const float4*)&g_part[((size_t)bx * B_BATCH + b) * 16];
        float4 p0 = p[0], p1 = p[1], p2 = p[2], p3 = p[3];
        dn[0] += p0.x; dn[1] += p0.y; dn[2] += p0.z; dn[3] += p0.w;
        dn[4] += p1.x;
        dq[0] += p1.y; dq[1] += p1.z; dq[2] += p1.w;
        dq[3] += p2.x; dq[4] += p2.y; dq[5] += p2.z; dq[6] += p2.w;
        dq[7] += p3.x;
    }
    float l[8];
    for (int w = 0; w < k; ++w) l[w] = 2.5f * tanhf((dn[w] + bn[w]) * 0.2f);
    {
        const float* g0 = gum + ((size_t)(2 * s) * B_BATCH + b) * 8;
        float m = l[0]; for (int w = 1; w < k; ++w) m = fmaxf(m, l[w]);
        float sum = 0.f; for (int w = 0; w < k; ++w) sum += expf(l[w] - m);
        float lse = m + logf(sum);
        float ent = 0.f;
        for (int w = 0; w < k; ++w){ float lp = l[w] - lse; ent -= lp * expf(lp); }
        int a = 0; float best = l[0] + g0[0];
        for (int w = 1; w < k; ++w){ float v = l[w] + g0[w]; if (v > best){ best = v; a = w; } }
        int row = 2 * s;
        out[(size_t)row * B_BATCH + b]        = (float)a;
        out[(size_t)(16 + row) * B_BATCH + b] = l[a] - lse;
        out[(size_t)(32 + row) * B_BATCH + b] = ent;
    }
    for (int w = 0; w < 8; ++w) l[w] = (dq[w] + bop[w]) * 0.2f;
    {
        const float* g1 = gum + ((size_t)(2 * s + 1) * B_BATCH + b) * 8;
        float m = l[0]; for (int w = 1; w < 8; ++w) m = fmaxf(m, l[w]);
        float sum = 0.f; for (int w = 0; w < 8; ++w) sum += expf(l[w] - m);
        float lse = m + logf(sum);
        float ent = 0.f;
        for (int w = 0; w < 8; ++w){ float lp = l[w] - lse; ent -= lp * expf(lp); }
        int a = 0; float best = l[0] + g1[0];
        for (int w = 1; w < 8; ++w){ float v = l[w] + g1[w]; if (v > best){ best = v; a = w; } }
        int row = 2 * s + 1;
        out[(size_t)row * B_BATCH + b]        = (float)a;
        out[(size_t)(16 + row) * B_BATCH + b] = l[a] - lse;
        out[(size_t)(32 + row) * B_BATCH + b] = ent;
        g_tok[b] = a;
    }
}

// ---------------- host: tensormap construction via dlopen(libcuda) ----------------
typedef CUresult (*EncodeTiledFn)(CUtensorMap*, CUtensorMapDataType, cuuint32_t, void*,
                                  const cuuint64_t*, const cuuint64_t*, const cuuint32_t*,
                                  const cuuint32_t*, CUtensorMapInterleave, CUtensorMapSwizzle,
                                  CUtensorMapL2promotion, CUtensorMapFloatOOBfill);

static EncodeTiledFn get_encoder(){
    void* h = dlopen("libcuda.so.1", RTLD_LAZY | RTLD_GLOBAL);
    if (!h) h = dlopen("libcuda.so", RTLD_LAZY | RTLD_GLOBAL);
    if (!h) return nullptr;
    return (EncodeTiledFn)dlsym(h, "cuTensorMapEncodeTiled");
}

static void make_map(EncodeTiledFn enc, CUtensorMap* m, void* base,
                     uint64_t rows, uint32_t box_rows){
    cuuint64_t dims[2]    = {(cuuint64_t)HID, (cuuint64_t)rows};
    cuuint64_t strides[1] = {(cuuint64_t)HID * 4};
    cuuint32_t box[2]     = {KC, box_rows};
    cuuint32_t es[2]      = {1, 1};
    enc(m, CU_TENSOR_MAP_DATA_TYPE_FLOAT32, 2, base, dims, strides, box, es,
        CU_TENSOR_MAP_INTERLEAVE_NONE, CU_TENSOR_MAP_SWIZZLE_128B,
        CU_TENSOR_MAP_L2_PROMOTION_L2_128B, CU_TENSOR_MAP_FLOAT_OOB_FILL_NONE);
}

// ---------------- launch ----------------
extern "C" void kernel_launch(void* const* d_in, const int* in_sizes, int n_in,
                              void* d_out, int out_size){
    const float* emb  = (const float*)d_in[0];
    const float* w_ih = (const float*)d_in[1];
    const float* w_hh = (const float*)d_in[2];
    const float* b_ih = (const float*)d_in[3];
    const float* b_hh = (const float*)d_in[4];
    const float* wn[4] = {(const float*)d_in[5], (const float*)d_in[7],
                          (const float*)d_in[9], (const float*)d_in[11]};
    const float* bn[4] = {(const float*)d_in[6], (const float*)d_in[8],
                          (const float*)d_in[10], (const float*)d_in[12]};
    const float* wop = (const float*)d_in[13];
    const float* bop = (const float*)d_in[14];
    const float* gum = (const float*)d_in[15];
    float* out = (float*)d_out;

    EncodeTiledFn enc = get_encoder();
    void *pAh, *pAl, *pBh, *pBl, *pHd, *pCd;
    cudaGetSymbolAddress(&pAh, g_Ah);
    cudaGetSymbolAddress(&pAl, g_Al);
    cudaGetSymbolAddress(&pBh, g_Bh);
    cudaGetSymbolAddress(&pBl, g_Bl);
    cudaGetSymbolAddress(&pHd, g_Hd);
    cudaGetSymbolAddress(&pCd, g_Cd);
    CUtensorMap mAh[2], mAl[2], mBh, mBl;
    size_t buf = (size_t)B_BATCH * HID * 4;
    make_map(enc, &mAh[0], (char*)pAh,       B_BATCH, BM);
    make_map(enc, &mAh[1], (char*)pAh + buf, B_BATCH, BM);
    make_map(enc, &mAl[0], (char*)pAl,       B_BATCH, BM);
    make_map(enc, &mAl[1], (char*)pAl + buf, B_BATCH, BM);
    make_map(enc, &mBh, pBh, G4, BN);
    make_map(enc, &mBl, pBl, G4, BN);

    float* Hd0 = (float*)pHd;
    float* Hd1 = (float*)pHd + 512 * HID;
    float* Cd0 = (float*)pCd;
    float* Cd1 = (float*)pCd + 512 * HID;

    cudaFuncSetAttribute(mega_step, cudaFuncAttributeMaxDynamicSharedMemorySize, SMEM_TOTAL);

    precompute_E<<<dim3(G4 / 256, 9), 256>>>(emb, w_ih, b_ih, b_hh);
    split_B<<<G4, 256>>>(w_hh);

    step0_compute<<<1, 512>>>(wn[0], bn[0], wop, bop);
    step0_sample<<<B_BATCH / 256, 256>>>(gum, out);

    dstep_gemm<<<dim3(8, 1), 256>>>(w_hh, Hd0, 1);
    dstep_point<<<8, 128>>>(1, 2, wn[0], bn[0], wop, bop, Hd1, Cd1, Cd0);
    dsample<<<B_BATCH / 256, 256>>>(1, 8, 2, gum, out);

    dstep_gemm<<<dim3(8, 1), 256>>>(w_hh, Hd1, 8);
    dstep_point<<<64, 128>>>(8, 3, wn[1], bn[1], wop + 8 * HID, bop + 8, Hd0, Cd0, Cd1);
    dsample<<<B_BATCH / 256, 256>>>(2, 64, 3, gum, out);

    dstep_gemm<<<dim3(8, 8), 256>>>(w_hh, Hd0, 64);
    dstep_point<<<512, 128>>>(64, 3, wn[1], bn[1], wop + 8 * HID, bop + 8, Hd1, Cd1, Cd0);
    dsample<<<B_BATCH / 256, 256>>>(3, 512, 3, gum, out);

    // step 4: distinct 512-key GEMM + per-row pointwise with inline decide
    dstep_gemm<<<dim3(8, 64), 256>>>(w_hh, Hd1, 512);
    row_point4<<<B_BATCH, 128>>>(wn[2], bn[2], wop + (size_t)2 * 8 * HID, bop + 16, gum, out);

    mega_step<<<NWORK, 256, SMEM_TOTAL>>>(wn[2], wn[3], bn[2], bn[3], wop, bop, gum, out,
                                          mAh[0], mAh[1], mAl[0], mAl[1], mBh, mBl);

    finalize_kernel<<<B_BATCH / 256, 256>>>(bn[3], 5, bop + 24, gum, 7, out);
}